// round 6
// baseline (speedup 1.0000x reference)
#include <cuda_runtime.h>
#include <math.h>

// predictor_interp2d: nearest-bot gather onto 256x256 grid, 2-level Voronoi pruning.
//
// Inputs: d_in[0] = R_pc [B=2,C=4,N=1024] f32 ; d_in[1] = XY_pc [B=2,2,N=1024] f32
// Output: R_grd [B,C,256,256] f32
//
// Exact-match: per-cell argmin uses the reference-rounded formula
//   pn2 = rn(x*x)+rn(y*y); dot = fmaf(gy,y,rn(gx*x)); d2 = fmaf(-2,dot,pn2)
// scanned in ascending point order with strict '<' (first-min tie-break).
// Level 1 (16x16-cell tile):   keep p iff d(tc,p) <= dmin(tc) + 2*R_tile + 1e-3
// Level 2 (4x4-cell subtile):  keep p iff d(sc,p) <= dmin(sc) + 2*R_sub  + 1e-3
// Triangle inequality guarantees every possible winner/tie survives both
// levels; 1e-3 distance margin >> fp32 evaluation noise. Overflows fall back
// to the coarser (still exact) list.

#define GH 256
#define GW 256
#define NPTS 1024
#define NCH 4
#define TILE 16
#define TPB 256
#define TILES_PER_B 256
#define CAP 384
#define CAP_SUB 32
#define RTILE 0.041434f          // 7.5*sqrt(2)/256, rounded up
#define RSUB  0.008287f          // 1.5*sqrt(2)/256, rounded up

__global__ void __launch_bounds__(TPB, 5)
nn_voronoi_h2_kernel(const float* __restrict__ R,
                     const float* __restrict__ XY,
                     float* __restrict__ out)
{
    __shared__ float4 cand[CAP];                 // tile list (x,y,pn2,idx), asc n
    __shared__ float4 subl[16 * CAP_SUB];        // per-subtile lists
    __shared__ float s_red[8];
    __shared__ int   s_wtot[8];

    const int tid  = threadIdx.x;
    const int lane = tid & 31;
    const int warp = tid >> 5;

    const int b    = blockIdx.x >> 8;
    const int tile = blockIdx.x & 255;
    const int r0   = (tile >> 4) * TILE;
    const int c0   = (tile & 15) * TILE;

    const float* xp = XY + b * (2 * NPTS);
    const float* yp = xp + NPTS;

    // ================= Level 1: tile candidate list =================
    const float4 xv = *(const float4*)(xp + 4 * tid);
    const float4 yv = *(const float4*)(yp + 4 * tid);
    const float px[4] = { xv.x, xv.y, xv.z, xv.w };
    const float py[4] = { yv.x, yv.y, yv.z, yv.w };

    const float gcx = ((float)c0 + 8.0f) * (1.0f / GW);
    const float gcy = ((float)r0 + 8.0f) * (1.0f / GH);

    float d2r[4];
    float m = 3.4e38f;
#pragma unroll
    for (int i = 0; i < 4; ++i) {
        const float dx = gcx - px[i];
        const float dy = gcy - py[i];
        d2r[i] = __fmaf_rn(dy, dy, dx * dx);
        m = fminf(m, d2r[i]);
    }
#pragma unroll
    for (int o = 16; o > 0; o >>= 1)
        m = fminf(m, __shfl_xor_sync(0xffffffffu, m, o));
    if (lane == 0) s_red[warp] = m;
    __syncthreads();
    float d2min = s_red[0];
#pragma unroll
    for (int w = 1; w < 8; ++w) d2min = fminf(d2min, s_red[w]);

    const float T = sqrtf(d2min) + 2.0f * RTILE + 1.0e-3f;
    const float thresh2 = T * T;

    unsigned fl = 0;
#pragma unroll
    for (int i = 0; i < 4; ++i)
        fl |= (d2r[i] <= thresh2) ? (1u << i) : 0u;

    const int cnt = __popc(fl);
    int inc = cnt;
#pragma unroll
    for (int o = 1; o < 32; o <<= 1) {
        const int v = __shfl_up_sync(0xffffffffu, inc, o);
        if (lane >= o) inc += v;
    }
    if (lane == 31) s_wtot[warp] = inc;
    __syncthreads();
    int wpre = 0, total = 0;
#pragma unroll
    for (int w = 0; w < 8; ++w) {
        const int v = s_wtot[w];
        wpre += (w < warp) ? v : 0;
        total += v;
    }
    int pos = wpre + inc - cnt;

    const bool overflow = (total > CAP);
    if (!overflow && cnt) {
        const int nbase = 4 * tid;
#pragma unroll
        for (int i = 0; i < 4; ++i) {
            if ((fl >> i) & 1u) {
                const float x = px[i], y = py[i];
                const float pn2 = __fadd_rn(__fmul_rn(x, x), __fmul_rn(y, y));
                cand[pos++] = make_float4(x, y, pn2, __int_as_float(nbase + i));
            }
        }
    }
    __syncthreads();

    // ================= Level 2: per-4x4-subtile refine (half-warp) =========
    const int s  = tid >> 4;                 // subtile id 0..15
    const int j  = tid & 15;                 // lane within subtile group
    const unsigned gmask = (tid & 16) ? 0xFFFF0000u : 0x0000FFFFu;

    const int sr = (s >> 2) * 4;             // subtile origin within tile
    const int sc = (s & 3) * 4;
    const float scx = ((float)(c0 + sc) + 2.0f) * (1.0f / GW);
    const float scy = ((float)(r0 + sr) + 2.0f) * (1.0f / GH);

    float4* sub = subl + s * CAP_SUB;
    int  sub_total = 0;
    bool sub_ok = !overflow;

    if (!overflow) {
        const int nch = (total + 15) >> 4;   // strided chunks over tile list
        float d2c[4];                        // cache first 4 chunks (covers total<=64)
        float sm = 3.4e38f;
        for (int k = 0; k < nch; ++k) {
            const int i = k * 16 + j;
            float d2v = 3.0e38f;
            if (i < total) {
                const float4 q = cand[i];
                const float dx = scx - q.x;
                const float dy = scy - q.y;
                d2v = __fmaf_rn(dy, dy, dx * dx);
            }
            if (k < 4) d2c[k] = d2v;
            sm = fminf(sm, d2v);
        }
#pragma unroll
        for (int o = 8; o > 0; o >>= 1)      // 16-lane min (stays in half-warp)
            sm = fminf(sm, __shfl_xor_sync(0xffffffffu, sm, o));
        const float Ts = sqrtf(sm) + 2.0f * RSUB + 1.0e-3f;
        const float th2 = Ts * Ts;

        for (int k = 0; k < nch; ++k) {
            const int i = k * 16 + j;
            float d2v = 3.0e38f;
            if (k < 4) d2v = d2c[k];
            else if (i < total) {
                const float4 q = cand[i];
                const float dx = scx - q.x;
                const float dy = scy - q.y;
                d2v = __fmaf_rn(dy, dy, dx * dx);
            }
            const bool f = (d2v <= th2);
            const unsigned mb = __ballot_sync(0xffffffffu, f) & gmask;
            const int p = sub_total + __popc(mb & ((1u << lane) - 1u));
            if (f && p < CAP_SUB) sub[p] = cand[i];
            sub_total += __popc(mb);
        }
        if (sub_total > CAP_SUB) sub_ok = false;
    }
    __syncwarp();

    // ================= Phase B: exact argmin (reference rounding) ==========
    const int r = r0 + sr + (j >> 2);
    const int c = c0 + sc + (j & 3);
    const float gx = ((float)c + 0.5f) * (1.0f / GW);
    const float gy = ((float)r + 0.5f) * (1.0f / GH);

    float best = 3.4e38f;
    int   bn   = 0;

    if (!overflow) {
        const float4* lst = sub_ok ? sub : cand;
        const int     cb  = sub_ok ? sub_total : total;
        for (int i = 0; i < cb; ++i) {
            const float4 q = lst[i];
            const float dot = __fmaf_rn(gy, q.y, __fmul_rn(gx, q.x));
            const float d2  = __fmaf_rn(-2.0f, dot, q.z);
            if (d2 < best) { best = d2; bn = __float_as_int(q.w); }
        }
    } else {
        for (int n = 0; n < NPTS; ++n) {     // rare exact fallback
            const float x = __ldg(xp + n);
            const float y = __ldg(yp + n);
            const float pn2 = __fadd_rn(__fmul_rn(x, x), __fmul_rn(y, y));
            const float dot = __fmaf_rn(gy, y, __fmul_rn(gx, x));
            const float d2  = __fmaf_rn(-2.0f, dot, pn2);
            if (d2 < best) { best = d2; bn = n; }
        }
    }

    // ---- gather channels + store ----
    const float* Rb = R + b * (NCH * NPTS);
    const int g = r * GW + c;
#pragma unroll
    for (int ch = 0; ch < NCH; ++ch)
        out[(b * NCH + ch) * (GH * GW) + g] = __ldg(Rb + ch * NPTS + bn);
}

extern "C" void kernel_launch(void* const* d_in, const int* in_sizes, int n_in,
                              void* d_out, int out_size)
{
    const float* R  = (const float*)d_in[0];
    const float* XY = (const float*)d_in[1];
    nn_voronoi_h2_kernel<<<2 * TILES_PER_B, TPB>>>(R, XY, (float*)d_out);
}

// round 7
// speedup vs baseline: 2.1780x; 2.1780x over previous
#include <cuda_runtime.h>
#include <math.h>

// predictor_interp2d: nearest-bot gather onto a 256x256 grid, Voronoi-pruned.
//
// Inputs: d_in[0] = R_pc [B=2,C=4,N=1024] f32 ; d_in[1] = XY_pc [B=2,2,N=1024] f32
// Output: R_grd [B,C,256,256] f32
//
// Per-cell argmin uses the reference-rounded formula
//   pn2 = rn(x*x)+rn(y*y); dot = fmaf(gy,y,rn(gx*x)); d2 = fmaf(-2,dot,pn2)
// over a candidate subset scanned in ascending point order; tie-break = first
// (smallest index), bit-exact vs the JAX reference.
// Pruning per 16x16-cell tile: keep p iff
//   dist(tile_center,p) <= min_q dist(tile_center,q) + 2*R_tile + 1e-3
// (R_tile = 7.5*sqrt(2)/256). Pruned points are farther by >> fp noise, so
// they can neither win nor tie. Overflow -> full scan from gmem (exact).

#define GH 256
#define GW 256
#define NPTS 1024
#define NCH 4
#define TILE 16
#define TPB 256
#define TILES_PER_B 256
#define CAP 384                 // capacity incl. 3 sentinel slots
#define RTILE 0.041434f         // 7.5*sqrt(2)/256, rounded up

__global__ void __launch_bounds__(TPB, 6)
nn_voronoi_reg4_kernel(const float* __restrict__ R,
                       const float* __restrict__ XY,
                       float* __restrict__ out)
{
    __shared__ float4 cand[CAP];     // (x, y, pn2, idx-as-int), ascending n
    __shared__ float s_red[8];
    __shared__ int   s_wtot[8];

    const int tid  = threadIdx.x;
    const int lane = tid & 31;
    const int warp = tid >> 5;

    const int b    = blockIdx.x >> 8;
    const int tile = blockIdx.x & 255;
    const int r0   = (tile >> 4) * TILE;
    const int c0   = (tile & 15) * TILE;

    const float* xp = XY + b * (2 * NPTS);
    const float* yp = xp + NPTS;

    // ---- phase A: own 4 points in registers (2x LDG.128, coalesced) ----
    const float4 xv = *(const float4*)(xp + 4 * tid);
    const float4 yv = *(const float4*)(yp + 4 * tid);
    const float px[4] = { xv.x, xv.y, xv.z, xv.w };
    const float py[4] = { yv.x, yv.y, yv.z, yv.w };

    const float gcx = ((float)c0 + 8.0f) * (1.0f / GW);
    const float gcy = ((float)r0 + 8.0f) * (1.0f / GH);

    float d2r[4];
    float m = 3.4e38f;
#pragma unroll
    for (int i = 0; i < 4; ++i) {
        const float dx = gcx - px[i];
        const float dy = gcy - py[i];
        d2r[i] = __fmaf_rn(dy, dy, dx * dx);
        m = fminf(m, d2r[i]);
    }
#pragma unroll
    for (int o = 16; o > 0; o >>= 1)
        m = fminf(m, __shfl_xor_sync(0xffffffffu, m, o));
    if (lane == 0) s_red[warp] = m;
    __syncthreads();
    float d2min = s_red[0];
#pragma unroll
    for (int w = 1; w < 8; ++w) d2min = fminf(d2min, s_red[w]);

    const float T = sqrtf(d2min) + 2.0f * RTILE + 1.0e-3f;
    const float thresh2 = T * T;

    // ---- flag + ordered block compaction ----
    unsigned fl = 0;
#pragma unroll
    for (int i = 0; i < 4; ++i)
        fl |= (d2r[i] <= thresh2) ? (1u << i) : 0u;

    const int cnt = __popc(fl);
    int inc = cnt;
#pragma unroll
    for (int o = 1; o < 32; o <<= 1) {
        const int v = __shfl_up_sync(0xffffffffu, inc, o);
        if (lane >= o) inc += v;
    }
    if (lane == 31) s_wtot[warp] = inc;
    __syncthreads();
    int wpre = 0, total = 0;
#pragma unroll
    for (int w = 0; w < 8; ++w) {
        const int v = s_wtot[w];
        wpre += (w < warp) ? v : 0;
        total += v;
    }
    int pos = wpre + inc - cnt;

    const bool overflow = (total > CAP - 3);   // keep 3 sentinel slots
    if (!overflow) {
        if (cnt) {
            const int nbase = 4 * tid;
#pragma unroll
            for (int i = 0; i < 4; ++i) {
                if ((fl >> i) & 1u) {
                    const float x = px[i], y = py[i];
                    const float pn2 = __fadd_rn(__fmul_rn(x, x), __fmul_rn(y, y));
                    cand[pos++] = make_float4(x, y, pn2, __int_as_float(nbase + i));
                }
            }
        }
        if (tid < 3)                            // sentinels: never win
            cand[total + tid] =
                make_float4(0.0f, 0.0f, 3.0e38f, __int_as_float(NPTS + tid));
    }
    __syncthreads();

    // ---- phase B: exact argmin, 4 interleaved accumulators ----
    const int r = r0 + (tid >> 4);
    const int c = c0 + (tid & 15);
    const float gx = ((float)c + 0.5f) * (1.0f / GW);
    const float gy = ((float)r + 0.5f) * (1.0f / GH);

    int bn;
    if (!overflow) {
        float bd[4] = { 3.4e38f, 3.4e38f, 3.4e38f, 3.4e38f };
        int   bi[4] = { NPTS, NPTS, NPTS, NPTS };
        const int tr = (total + 3) & ~3;        // sentinels pad the tail
        for (int i = 0; i < tr; i += 4) {
#pragma unroll
            for (int k = 0; k < 4; ++k) {
                const float4 q = cand[i + k];
                const float d2 = __fmaf_rn(
                    -2.0f, __fmaf_rn(gy, q.y, __fmul_rn(gx, q.x)), q.z);
                if (d2 < bd[k]) { bd[k] = d2; bi[k] = __float_as_int(q.w); }
            }
        }
        // merge by (d2, idx): indices are globally unique & ascending within
        // each lane's positions, so this reproduces first-min tie-breaking.
        float b0 = bd[0]; int i0 = bi[0];
        if (bd[1] < b0 || (bd[1] == b0 && bi[1] < i0)) { b0 = bd[1]; i0 = bi[1]; }
        float b1 = bd[2]; int i1 = bi[2];
        if (bd[3] < b1 || (bd[3] == b1 && bi[3] < i1)) { b1 = bd[3]; i1 = bi[3]; }
        bn = (b1 < b0 || (b1 == b0 && i1 < i0)) ? i1 : i0;
    } else {
        float best = 3.4e38f; bn = 0;
        for (int n = 0; n < NPTS; ++n) {        // rare exact fallback
            const float x = __ldg(xp + n);
            const float y = __ldg(yp + n);
            const float pn2 = __fadd_rn(__fmul_rn(x, x), __fmul_rn(y, y));
            const float dot = __fmaf_rn(gy, y, __fmul_rn(gx, x));
            const float d2  = __fmaf_rn(-2.0f, dot, pn2);
            if (d2 < best) { best = d2; bn = n; }
        }
    }

    // ---- gather channels + store ----
    const float* Rb = R + b * (NCH * NPTS);
    const int g = r * GW + c;
#pragma unroll
    for (int ch = 0; ch < NCH; ++ch)
        out[(b * NCH + ch) * (GH * GW) + g] = __ldg(Rb + ch * NPTS + bn);
}

extern "C" void kernel_launch(void* const* d_in, const int* in_sizes, int n_in,
                              void* d_out, int out_size)
{
    const float* R  = (const float*)d_in[0];
    const float* XY = (const float*)d_in[1];
    nn_voronoi_reg4_kernel<<<2 * TILES_PER_B, TPB>>>(R, XY, (float*)d_out);
}

// round 10
// speedup vs baseline: 2.6214x; 1.2036x over previous
#include <cuda_runtime.h>
#include <math.h>

// predictor_interp2d: nearest-bot gather onto a 256x256 grid.
// Two-level Voronoi pruning: 16x16-cell tile list (block), then a register-only
// warp-level refine over an 8x4-cell region, then exact per-cell argmin.
//
// Inputs: d_in[0] = R_pc [B=2,C=4,N=1024] f32 ; d_in[1] = XY_pc [B=2,2,N=1024] f32
// Output: R_grd [B,C,256,256] f32
//
// Exactness: final argmin uses the reference-rounded formula
//   pn2 = rn(x*x)+rn(y*y); dot = fmaf(gy,y,rn(gx*x)); d2 = fmaf(-2,dot,pn2)
// scanned in ascending point order with strict '<' (first-min tie-break).
// Level 1 (tile): keep p iff d(tc,p) <= dmin(tc) + 2*R_tile + 1e-3.
// Level 2 (warp region): keep p iff d(wc,p) <= dmin(wc) + 2*R_warp + 1e-3,
//   where dmin(wc) is the min over the tile list (the warp center's true NN is
//   provably in the tile list: d(tc,nn) <= dmin(tc) + 2*d(tc,wc) <= thresh).
// 1e-3 distance margin >> fp32 noise, so no possible winner or tie is pruned.
// Overflow fallbacks stay exact (full tile list / full gmem scan).

#define GH 256
#define GW 256
#define NPTS 1024
#define NCH 4
#define TILE 16
#define TPB 256
#define TILES_PER_B 256
#define CAP 384
#define RTILE 0.041434f          // 7.5*sqrt(2)/256, rounded up
#define RWARP 0.014874f          // sqrt(7^2+3^2)/2/256, rounded up

__global__ void __launch_bounds__(TPB, 6)
nn_voronoi_wr_kernel(const float* __restrict__ R,
                     const float* __restrict__ XY,
                     float* __restrict__ out)
{
    __shared__ float4 cand[CAP];     // (x, y, pn2, idx-as-int), ascending n
    __shared__ float s_red[8];
    __shared__ int   s_wtot[8];

    const int tid  = threadIdx.x;
    const int lane = tid & 31;
    const int warp = tid >> 5;

    const int b    = blockIdx.x >> 8;
    const int tile = blockIdx.x & 255;
    const int r0   = (tile >> 4) * TILE;
    const int c0   = (tile & 15) * TILE;

    const float* xp = XY + b * (2 * NPTS);
    const float* yp = xp + NPTS;

    // ---- level 1: own 4 points in registers (2x LDG.128, coalesced) ----
    const float4 xv = *(const float4*)(xp + 4 * tid);
    const float4 yv = *(const float4*)(yp + 4 * tid);
    const float px[4] = { xv.x, xv.y, xv.z, xv.w };
    const float py[4] = { yv.x, yv.y, yv.z, yv.w };

    const float gcx = ((float)c0 + 8.0f) * (1.0f / GW);
    const float gcy = ((float)r0 + 8.0f) * (1.0f / GH);

    float d2r[4];
    float m = 3.4e38f;
#pragma unroll
    for (int i = 0; i < 4; ++i) {
        const float dx = gcx - px[i];
        const float dy = gcy - py[i];
        d2r[i] = __fmaf_rn(dy, dy, dx * dx);
        m = fminf(m, d2r[i]);
    }
#pragma unroll
    for (int o = 16; o > 0; o >>= 1)
        m = fminf(m, __shfl_xor_sync(0xffffffffu, m, o));
    if (lane == 0) s_red[warp] = m;
    __syncthreads();
    float d2min = s_red[0];
#pragma unroll
    for (int w = 1; w < 8; ++w) d2min = fminf(d2min, s_red[w]);

    const float T = sqrtf(d2min) + 2.0f * RTILE + 1.0e-3f;
    const float thresh2 = T * T;

    // ---- flag + ordered block compaction into tile list ----
    unsigned fl = 0;
#pragma unroll
    for (int i = 0; i < 4; ++i)
        fl |= (d2r[i] <= thresh2) ? (1u << i) : 0u;

    const int cnt = __popc(fl);
    int inc = cnt;
#pragma unroll
    for (int o = 1; o < 32; o <<= 1) {
        const int v = __shfl_up_sync(0xffffffffu, inc, o);
        if (lane >= o) inc += v;
    }
    if (lane == 31) s_wtot[warp] = inc;
    __syncthreads();
    int wpre = 0, total = 0;
#pragma unroll
    for (int w = 0; w < 8; ++w) {
        const int v = s_wtot[w];
        wpre += (w < warp) ? v : 0;
        total += v;
    }
    int pos = wpre + inc - cnt;

    const bool overflow = (total > CAP);
    if (!overflow && cnt) {
        const int nbase = 4 * tid;
#pragma unroll
        for (int i = 0; i < 4; ++i) {
            if ((fl >> i) & 1u) {
                const float x = px[i], y = py[i];
                const float pn2 = __fadd_rn(__fmul_rn(x, x), __fmul_rn(y, y));
                cand[pos++] = make_float4(x, y, pn2, __int_as_float(nbase + i));
            }
        }
    }
    __syncthreads();

    // ---- level 2: warp-region refine (registers + ballot, no smem) ----
    // warp covers 4 rows x 8 cols of cells
    const int wr = (warp >> 1) * 4;          // region row origin within tile
    const int wcc = (warp & 1) * 8;          // region col origin within tile
    const int r = r0 + wr + (lane >> 3);
    const int c = c0 + wcc + (lane & 7);

    int bn = 0;
    if (!overflow) {
        const bool small = (total <= 128);
        unsigned masks[4] = {0u, 0u, 0u, 0u};
        int nch = 0;
        if (small) {
            const float wcx = ((float)(c0 + wcc) + 3.5f + 0.5f) * (1.0f / GW);
            const float wcy = ((float)(r0 + wr)  + 1.5f + 0.5f) * (1.0f / GH);
            nch = (total + 31) >> 5;
            float d2c[4];
            float sm = 3.4e38f;
#pragma unroll
            for (int k = 0; k < 4; ++k) {
                d2c[k] = 3.0e38f;
                const int i = (k << 5) + lane;
                if (k < nch && i < total) {
                    const float4 q = cand[i];
                    const float dx = wcx - q.x;
                    const float dy = wcy - q.y;
                    d2c[k] = __fmaf_rn(dy, dy, dx * dx);
                }
                sm = fminf(sm, d2c[k]);
            }
#pragma unroll
            for (int o = 16; o > 0; o >>= 1)
                sm = fminf(sm, __shfl_xor_sync(0xffffffffu, sm, o));
            const float Tw = sqrtf(sm) + 2.0f * RWARP + 1.0e-3f;
            const float th2 = Tw * Tw;
#pragma unroll
            for (int k = 0; k < 4; ++k)
                masks[k] = __ballot_sync(0xffffffffu, d2c[k] <= th2);
        }

        // ---- exact per-cell argmin (reference rounding) ----
        const float gx = ((float)c + 0.5f) * (1.0f / GW);
        const float gy = ((float)r + 0.5f) * (1.0f / GH);
        float best = 3.4e38f;

        if (small) {
            for (int k = 0; k < nch; ++k) {
                unsigned mb = masks[k];
                const int base = k << 5;
                while (mb) {
                    const int bit = __ffs(mb) - 1;
                    mb &= mb - 1u;
                    const float4 q = cand[base + bit];      // broadcast LDS.128
                    const float dot = __fmaf_rn(gy, q.y, __fmul_rn(gx, q.x));
                    const float d2  = __fmaf_rn(-2.0f, dot, q.z);
                    if (d2 < best) { best = d2; bn = __float_as_int(q.w); }
                }
            }
        } else {
            for (int i = 0; i < total; ++i) {
                const float4 q = cand[i];
                const float dot = __fmaf_rn(gy, q.y, __fmul_rn(gx, q.x));
                const float d2  = __fmaf_rn(-2.0f, dot, q.z);
                if (d2 < best) { best = d2; bn = __float_as_int(q.w); }
            }
        }
    } else {
        // rare exact fallback: full scan from gmem
        const float gx = ((float)c + 0.5f) * (1.0f / GW);
        const float gy = ((float)r + 0.5f) * (1.0f / GH);
        float best = 3.4e38f;
        for (int n = 0; n < NPTS; ++n) {
            const float x = __ldg(xp + n);
            const float y = __ldg(yp + n);
            const float pn2 = __fadd_rn(__fmul_rn(x, x), __fmul_rn(y, y));
            const float dot = __fmaf_rn(gy, y, __fmul_rn(gx, x));
            const float d2  = __fmaf_rn(-2.0f, dot, pn2);
            if (d2 < best) { best = d2; bn = n; }
        }
    }

    // ---- gather channels + store ----
    const float* Rb = R + b * (NCH * NPTS);
    const int g = r * GW + c;
#pragma unroll
    for (int ch = 0; ch < NCH; ++ch)
        out[(b * NCH + ch) * (GH * GW) + g] = __ldg(Rb + ch * NPTS + bn);
}

extern "C" void kernel_launch(void* const* d_in, const int* in_sizes, int n_in,
                              void* d_out, int out_size)
{
    const float* R  = (const float*)d_in[0];
    const float* XY = (const float*)d_in[1];
    nn_voronoi_wr_kernel<<<2 * TILES_PER_B, TPB>>>(R, XY, (float*)d_out);
}

// round 11
// speedup vs baseline: 2.6308x; 1.0036x over previous
#include <cuda_runtime.h>
#include <math.h>

// predictor_interp2d: nearest-bot gather onto a 256x256 grid.
// Fixed-radius Voronoi pruning with a-posteriori exactness check:
//   Level 1 (16x16-cell tile): keep p iff d(tile_center,p) <= RFIX  (no block
//     reduction needed). After the per-cell argmin, each cell verifies
//     sqrt(true_d2_best) + R_TILE + 5e-3 <= RFIX; if so, the RFIX disk provably
//     contained every possible winner/tie (triangle inequality; margins >> fp
//     noise). Otherwise that cell does an exact full scan from gmem.
//   Level 2 (warp 8x4-cell region): register/ballot refine,
//     keep p iff d(wc,p) <= min_list d(wc,q) + 2*R_WARP + 1e-3  (exact, std proof).
// Final argmin uses the reference-rounded formula
//   pn2 = rn(x*x)+rn(y*y); dot = fmaf(gy,y,rn(gx*x)); d2 = fmaf(-2,dot,pn2)
// scanned in ascending point order with strict '<' (first-min tie-break),
// bit-exact vs the JAX reference.

#define GH 256
#define GW 256
#define NPTS 1024
#define NCH 4
#define TILE 16
#define TPB 256
#define TILES_PER_B 256
#define CAP 256
#define RFIX  0.12f
#define RTILE 0.041434f          // 7.5*sqrt(2)/256, rounded up
#define RWARP 0.014875f          // sqrt(1.5^2+3.5^2)/256, rounded up

__global__ void __launch_bounds__(TPB, 6)
nn_voronoi_fix_kernel(const float* __restrict__ R,
                      const float* __restrict__ XY,
                      float* __restrict__ out)
{
    __shared__ float4 cand[CAP];     // (x, y, pn2, idx-as-int), ascending n
    __shared__ int s_wtot[8];

    const int tid  = threadIdx.x;
    const int lane = tid & 31;
    const int warp = tid >> 5;

    const int b    = blockIdx.x >> 8;
    const int tile = blockIdx.x & 255;
    const int r0   = (tile >> 4) * TILE;
    const int c0   = (tile & 15) * TILE;

    const float* xp = XY + b * (2 * NPTS);
    const float* yp = xp + NPTS;

    // ---- level 1: own 4 points in registers, fixed-radius flag ----
    const float4 xv = *(const float4*)(xp + 4 * tid);
    const float4 yv = *(const float4*)(yp + 4 * tid);
    const float px[4] = { xv.x, xv.y, xv.z, xv.w };
    const float py[4] = { yv.x, yv.y, yv.z, yv.w };

    const float gcx = ((float)c0 + 8.0f) * (1.0f / GW);
    const float gcy = ((float)r0 + 8.0f) * (1.0f / GH);

    unsigned fl = 0;
#pragma unroll
    for (int i = 0; i < 4; ++i) {
        const float dx = gcx - px[i];
        const float dy = gcy - py[i];
        const float d2 = __fmaf_rn(dy, dy, dx * dx);
        fl |= (d2 <= RFIX * RFIX) ? (1u << i) : 0u;
    }

    // ---- ordered block compaction (warp prefix + cross-warp totals) ----
    const int cnt = __popc(fl);
    int inc = cnt;
#pragma unroll
    for (int o = 1; o < 32; o <<= 1) {
        const int v = __shfl_up_sync(0xffffffffu, inc, o);
        if (lane >= o) inc += v;
    }
    if (lane == 31) s_wtot[warp] = inc;
    __syncthreads();
    int wpre = 0, total = 0;
#pragma unroll
    for (int w = 0; w < 8; ++w) {
        const int v = s_wtot[w];
        wpre += (w < warp) ? v : 0;
        total += v;
    }
    int pos = wpre + inc - cnt;

    const bool overflow = (total > CAP);
    if (!overflow && cnt) {
        const int nbase = 4 * tid;
#pragma unroll
        for (int i = 0; i < 4; ++i) {
            if ((fl >> i) & 1u) {
                const float x = px[i], y = py[i];
                const float pn2 = __fadd_rn(__fmul_rn(x, x), __fmul_rn(y, y));
                cand[pos++] = make_float4(x, y, pn2, __int_as_float(nbase + i));
            }
        }
    }
    __syncthreads();

    // ---- cell coordinates (warp covers 4 rows x 8 cols) ----
    const int wr  = (warp >> 1) * 4;
    const int wcc = (warp & 1) * 8;
    const int r = r0 + wr + (lane >> 3);
    const int c = c0 + wcc + (lane & 7);
    const float gx = ((float)c + 0.5f) * (1.0f / GW);
    const float gy = ((float)r + 0.5f) * (1.0f / GH);

    int   bn   = 0;
    float best = 3.4e38f;
    bool  need_full = overflow;

    if (!overflow) {
        const bool small = (total <= 128);
        unsigned masks[4] = {0u, 0u, 0u, 0u};
        int nch = 0;
        if (small) {
            // ---- level 2: warp-region refine (strided eval + ballot) ----
            const float wcx = ((float)(c0 + wcc) + 4.0f) * (1.0f / GW);
            const float wcy = ((float)(r0 + wr)  + 2.0f) * (1.0f / GH);
            nch = (total + 31) >> 5;
            float d2c[4];
            float sm = 3.4e38f;
#pragma unroll
            for (int k = 0; k < 4; ++k) {
                d2c[k] = 3.0e38f;
                const int i = (k << 5) + lane;
                if (k < nch && i < total) {
                    const float4 q = cand[i];
                    const float dx = wcx - q.x;
                    const float dy = wcy - q.y;
                    d2c[k] = __fmaf_rn(dy, dy, dx * dx);
                }
                sm = fminf(sm, d2c[k]);
            }
#pragma unroll
            for (int o = 16; o > 0; o >>= 1)
                sm = fminf(sm, __shfl_xor_sync(0xffffffffu, sm, o));
            const float Tw = sqrtf(sm) + 2.0f * RWARP + 1.0e-3f;
            const float th2 = Tw * Tw;
#pragma unroll
            for (int k = 0; k < 4; ++k)
                masks[k] = __ballot_sync(0xffffffffu, d2c[k] <= th2);

            // ---- exact argmin over refined set (ascending index) ----
            for (int k = 0; k < nch; ++k) {
                unsigned mb = masks[k];
                const int base = k << 5;
                while (mb) {
                    const int bit = __ffs(mb) - 1;
                    mb &= mb - 1u;
                    const float4 q = cand[base + bit];
                    const float dot = __fmaf_rn(gy, q.y, __fmul_rn(gx, q.x));
                    const float d2  = __fmaf_rn(-2.0f, dot, q.z);
                    if (d2 < best) { best = d2; bn = __float_as_int(q.w); }
                }
            }
        } else {
            for (int i = 0; i < total; ++i) {
                const float4 q = cand[i];
                const float dot = __fmaf_rn(gy, q.y, __fmul_rn(gx, q.x));
                const float d2  = __fmaf_rn(-2.0f, dot, q.z);
                if (d2 < best) { best = d2; bn = __float_as_int(q.w); }
            }
        }

        // ---- a-posteriori exactness check (per cell, local) ----
        const float g2 = __fmaf_rn(gy, gy, gx * gx);
        const float dtrue = sqrtf(fmaxf(best + g2, 0.0f));
        need_full = (dtrue + RTILE + 5.0e-3f > RFIX);
    }

    if (need_full) {
        // exact full scan from gmem (vanishingly rare)
        best = 3.4e38f; bn = 0;
        for (int n = 0; n < NPTS; ++n) {
            const float x = __ldg(xp + n);
            const float y = __ldg(yp + n);
            const float pn2 = __fadd_rn(__fmul_rn(x, x), __fmul_rn(y, y));
            const float dot = __fmaf_rn(gy, y, __fmul_rn(gx, x));
            const float d2  = __fmaf_rn(-2.0f, dot, pn2);
            if (d2 < best) { best = d2; bn = n; }
        }
    }

    // ---- gather channels + store ----
    const float* Rb = R + b * (NCH * NPTS);
    const int g = r * GW + c;
#pragma unroll
    for (int ch = 0; ch < NCH; ++ch)
        out[(b * NCH + ch) * (GH * GW) + g] = __ldg(Rb + ch * NPTS + bn);
}

extern "C" void kernel_launch(void* const* d_in, const int* in_sizes, int n_in,
                              void* d_out, int out_size)
{
    const float* R  = (const float*)d_in[0];
    const float* XY = (const float*)d_in[1];
    nn_voronoi_fix_kernel<<<2 * TILES_PER_B, TPB>>>(R, XY, (float*)d_out);
}

// round 12
// speedup vs baseline: 2.7085x; 1.0295x over previous
#include <cuda_runtime.h>
#include <math.h>

// predictor_interp2d: nearest-bot gather onto a 256x256 grid.
// Fixed-radius tile pruning + half-warp 4x4-subtile refine, exact argmin.
//
// Inputs: d_in[0] = R_pc [B=2,C=4,N=1024] f32 ; d_in[1] = XY_pc [B=2,2,N=1024] f32
// Output: R_grd [B,C,256,256] f32
//
// Level 1 (16x16 tile): keep p iff d(tile_center,p) <= RFIX (no reduction).
//   A-posteriori per-cell check: sqrt(true_d2) + R_TILE + 5e-3 <= RFIX proves
//   every possible winner/tie was inside the RFIX disk (triangle inequality,
//   margins >> fp32 noise); failing cells do an exact full gmem scan.
// Level 2 (4x4 subtile, one half-warp each): keep p iff
//   d(sc,p) <= min_{q in tile list} d(sc,q) + 2*R_SUB + 1e-3
//   (valid over any list; winner w in list satisfies d(sc,w) <= dmin+2*R_SUB).
// Final argmin uses the reference-rounded formula
//   pn2 = rn(x*x)+rn(y*y); dot = fmaf(gy,y,rn(gx*x)); d2 = fmaf(-2,dot,pn2)
// scanned in ascending point order with strict '<' (first-min tie-break),
// bit-exact vs the JAX reference. All fallback paths exact.

#define GH 256
#define GW 256
#define NPTS 1024
#define NCH 4
#define TILE 16
#define TPB 256
#define CAP 256
#define SUBCAP 16
#define RFIX  0.12f
#define RTILE 0.041434f          // 7.5*sqrt(2)/256, rounded up
#define RSUB  0.008287f          // 1.5*sqrt(2)/256, rounded up

__global__ void __launch_bounds__(TPB, 6)
nn_fix_sub_kernel(const float* __restrict__ R,
                  const float* __restrict__ XY,
                  float* __restrict__ out)
{
    __shared__ float4 cand[CAP];            // tile list (x,y,pn2,idx), asc n
    __shared__ float4 subl[16 * SUBCAP];    // per-subtile refined lists (4KB)
    __shared__ int s_wtot[8];

    const int tid  = threadIdx.x;
    const int lane = tid & 31;
    const int warp = tid >> 5;

    const int b    = blockIdx.x >> 8;
    const int tile = blockIdx.x & 255;
    const int r0   = (tile >> 4) * TILE;
    const int c0   = (tile & 15) * TILE;

    const float* xp = XY + b * (2 * NPTS);
    const float* yp = xp + NPTS;

    // ---- level 1: own 4 points in registers, fixed-radius flag ----
    const float4 xv = *(const float4*)(xp + 4 * tid);
    const float4 yv = *(const float4*)(yp + 4 * tid);
    const float px[4] = { xv.x, xv.y, xv.z, xv.w };
    const float py[4] = { yv.x, yv.y, yv.z, yv.w };

    const float gcx = ((float)c0 + 8.0f) * (1.0f / GW);
    const float gcy = ((float)r0 + 8.0f) * (1.0f / GH);

    unsigned fl = 0;
#pragma unroll
    for (int i = 0; i < 4; ++i) {
        const float dx = gcx - px[i];
        const float dy = gcy - py[i];
        const float d2 = __fmaf_rn(dy, dy, dx * dx);
        fl |= (d2 <= RFIX * RFIX) ? (1u << i) : 0u;
    }

    // ---- ordered block compaction into the tile list ----
    const int cnt = __popc(fl);
    int inc = cnt;
#pragma unroll
    for (int o = 1; o < 32; o <<= 1) {
        const int v = __shfl_up_sync(0xffffffffu, inc, o);
        if (lane >= o) inc += v;
    }
    if (lane == 31) s_wtot[warp] = inc;
    __syncthreads();
    int wpre = 0, total = 0;
#pragma unroll
    for (int w = 0; w < 8; ++w) {
        const int v = s_wtot[w];
        wpre += (w < warp) ? v : 0;
        total += v;
    }
    int pos = wpre + inc - cnt;

    const bool overflow = (total > CAP);
    if (!overflow && cnt) {
        const int nbase = 4 * tid;
#pragma unroll
        for (int i = 0; i < 4; ++i) {
            if ((fl >> i) & 1u) {
                const float x = px[i], y = py[i];
                const float pn2 = __fadd_rn(__fmul_rn(x, x), __fmul_rn(y, y));
                cand[pos++] = make_float4(x, y, pn2, __int_as_float(nbase + i));
            }
        }
    }
    __syncthreads();

    // ---- level 2: 4x4-subtile refine, one half-warp per subtile ----
    const int s = tid >> 4;                  // subtile 0..15
    const int j = tid & 15;                  // lane within half-warp
    const unsigned gmask = (tid & 16) ? 0xFFFF0000u : 0x0000FFFFu;
    const int sr = (s >> 2) * 4;
    const int sc = (s & 3) * 4;

    const int r = r0 + sr + (j >> 2);
    const int c = c0 + sc + (j & 3);
    const float gx = ((float)c + 0.5f) * (1.0f / GW);
    const float gy = ((float)r + 0.5f) * (1.0f / GH);

    float best = 3.4e38f;
    int   bn   = 0;
    bool  need_full = overflow;

    if (!overflow) {
        float4* sub = subl + s * SUBCAP;
        int sub_total = -1;                  // -1 => refine unavailable
        if (total <= 64) {                   // 4 strided chunks cover the list
            const float scx = ((float)(c0 + sc) + 2.0f) * (1.0f / GW);
            const float scy = ((float)(r0 + sr) + 2.0f) * (1.0f / GH);
            float d2c[4];
            float sm = 3.0e38f;
#pragma unroll
            for (int k = 0; k < 4; ++k) {
                d2c[k] = 3.0e38f;
                const int i = (k << 4) + j;
                if (i < total) {
                    const float4 q = cand[i];
                    const float dx = scx - q.x;
                    const float dy = scy - q.y;
                    d2c[k] = __fmaf_rn(dy, dy, dx * dx);
                }
                sm = fminf(sm, d2c[k]);
            }
#pragma unroll
            for (int o = 8; o > 0; o >>= 1)      // min within half-warp
                sm = fminf(sm, __shfl_xor_sync(0xffffffffu, sm, o, 16));
            const float Ts = sqrtf(sm) + 2.0f * RSUB + 1.0e-3f;
            const float th2 = Ts * Ts;

            sub_total = 0;
#pragma unroll
            for (int k = 0; k < 4; ++k) {        // ordered (asc index) compaction
                const bool f = (d2c[k] <= th2);
                const unsigned mb = __ballot_sync(0xffffffffu, f) & gmask;
                const int p = sub_total + __popc(mb & ((1u << lane) - 1u));
                if (f && p < SUBCAP) sub[p] = cand[(k << 4) + j];
                sub_total += __popc(mb);
            }
            if (sub_total > SUBCAP) sub_total = -1;
        }
        __syncwarp();

        // ---- exact per-cell argmin (reference rounding, ascending index) ----
        const float4* lst = (sub_total >= 0) ? sub : cand;
        const int     cb  = (sub_total >= 0) ? sub_total : total;
        for (int i = 0; i < cb; ++i) {
            const float4 q = lst[i];
            const float dot = __fmaf_rn(gy, q.y, __fmul_rn(gx, q.x));
            const float d2  = __fmaf_rn(-2.0f, dot, q.z);
            if (d2 < best) { best = d2; bn = __float_as_int(q.w); }
        }

        // ---- a-posteriori exactness check for the fixed radius ----
        const float g2 = __fmaf_rn(gy, gy, gx * gx);
        const float dtrue = sqrtf(fmaxf(best + g2, 0.0f));
        need_full = (dtrue + RTILE + 5.0e-3f > RFIX);
    }

    if (need_full) {                         // exact full scan (vanishingly rare)
        best = 3.4e38f; bn = 0;
        for (int n = 0; n < NPTS; ++n) {
            const float x = __ldg(xp + n);
            const float y = __ldg(yp + n);
            const float pn2 = __fadd_rn(__fmul_rn(x, x), __fmul_rn(y, y));
            const float dot = __fmaf_rn(gy, y, __fmul_rn(gx, x));
            const float d2  = __fmaf_rn(-2.0f, dot, pn2);
            if (d2 < best) { best = d2; bn = n; }
        }
    }

    // ---- gather channels + store ----
    const float* Rb = R + b * (NCH * NPTS);
    const int g = r * GW + c;
#pragma unroll
    for (int ch = 0; ch < NCH; ++ch)
        out[(b * NCH + ch) * (GH * GW) + g] = __ldg(Rb + ch * NPTS + bn);
}

extern "C" void kernel_launch(void* const* d_in, const int* in_sizes, int n_in,
                              void* d_out, int out_size)
{
    const float* R  = (const float*)d_in[0];
    const float* XY = (const float*)d_in[1];
    nn_fix_sub_kernel<<<512, TPB>>>(R, XY, (float*)d_out);
}

// round 13
// speedup vs baseline: 2.7185x; 1.0037x over previous
#include <cuda_runtime.h>
#include <math.h>

// predictor_interp2d: nearest-bot gather onto a 256x256 grid.
// Single-barrier design: fixed-radius tile pruning into PER-WARP segments,
// half-warp 4x4-subtile refine with direct slot->segment mapping, fused
// ballot + exact argmin. One __syncthreads total.
//
// Inputs: d_in[0] = R_pc [B=2,C=4,N=1024] f32 ; d_in[1] = XY_pc [B=2,2,N=1024] f32
// Output: R_grd [B,C,256,256] f32
//
// Exactness:
//  - Level 1 (16x16 tile): keep p iff d(tile_center,p) <= RFIX. A-posteriori
//    per-cell check sqrt(true_d2)+R_TILE+5e-3 <= RFIX proves the RFIX disk
//    contained every possible winner/tie (triangle inequality, margins >> fp
//    noise); failing cells do an exact full gmem scan.
//  - Level 2 (4x4 subtile): keep p iff d(sc,p) <= min_list d(sc,q) + 2*R_SUB
//    + 1e-3 (standard bound over the whole candidate list).
//  - Final argmin uses the reference-rounded formula
//      pn2 = rn(x*x)+rn(y*y); dot = fmaf(gy,y,rn(gx*x)); d2 = fmaf(-2,dot,pn2)
//    scanned in ascending point order with strict '<' (first-min tie-break),
//    bit-exact vs the JAX reference. Segment overflow -> exact full scan.

#define GH 256
#define GW 256
#define NPTS 1024
#define NCH 4
#define TILE 16
#define TPB 256
#define SEGCAP 32
#define RFIX  0.12f
#define RTILE 0.041434f          // 7.5*sqrt(2)/256, rounded up
#define RSUB  0.008287f          // 1.5*sqrt(2)/256, rounded up

__global__ void __launch_bounds__(TPB, 4)
nn_seg_kernel(const float* __restrict__ R,
              const float* __restrict__ XY,
              float* __restrict__ out)
{
    __shared__ float4 seg[8 * SEGCAP];   // per-warp segments (x,y,pn2,idx), asc n
    __shared__ int s_cnt[8];

    const int tid  = threadIdx.x;
    const int lane = tid & 31;
    const int warp = tid >> 5;

    const int b    = blockIdx.x >> 8;
    const int tile = blockIdx.x & 255;
    const int r0   = (tile >> 4) * TILE;
    const int c0   = (tile & 15) * TILE;

    const float* xp = XY + b * (2 * NPTS);
    const float* yp = xp + NPTS;

    // ---- level 1: own 4 points in registers, fixed-radius flag ----
    const float4 xv = *(const float4*)(xp + 4 * tid);
    const float4 yv = *(const float4*)(yp + 4 * tid);
    const float px[4] = { xv.x, xv.y, xv.z, xv.w };
    const float py[4] = { yv.x, yv.y, yv.z, yv.w };

    const float gcx = ((float)c0 + 8.0f) * (1.0f / GW);
    const float gcy = ((float)r0 + 8.0f) * (1.0f / GH);

    unsigned fl = 0;
#pragma unroll
    for (int i = 0; i < 4; ++i) {
        const float dx = gcx - px[i];
        const float dy = gcy - py[i];
        const float d2 = __fmaf_rn(dy, dy, dx * dx);
        fl |= (d2 <= RFIX * RFIX) ? (1u << i) : 0u;
    }

    // ---- warp-local ordered compaction into this warp's segment ----
    const int cl = __popc(fl);
    int inc = cl;
#pragma unroll
    for (int o = 1; o < 32; o <<= 1) {
        const int v = __shfl_up_sync(0xffffffffu, inc, o);
        if (lane >= o) inc += v;
    }
    if (lane == 31) s_cnt[warp] = inc;       // warp candidate count
    int pos = inc - cl;
    if (cl) {
        float4* wseg = seg + warp * SEGCAP;
        const int nbase = 4 * tid;
#pragma unroll
        for (int i = 0; i < 4; ++i) {
            if ((fl >> i) & 1u) {
                if (pos < SEGCAP) {
                    const float x = px[i], y = py[i];
                    const float pn2 = __fadd_rn(__fmul_rn(x, x), __fmul_rn(y, y));
                    wseg[pos] = make_float4(x, y, pn2, __int_as_float(nbase + i));
                }
                ++pos;
            }
        }
    }
    __syncthreads();                          // the ONLY block barrier

    int cnt[8];
    bool ovf = false;
#pragma unroll
    for (int t = 0; t < 8; ++t) { cnt[t] = s_cnt[t]; ovf |= (cnt[t] > SEGCAP); }

    // ---- subtile geometry: half-warp per 4x4 subtile ----
    const int s = tid >> 4;                   // subtile 0..15
    const int j = tid & 15;
    const unsigned gmask = (tid & 16) ? 0xFFFF0000u : 0x0000FFFFu;
    const int sr = (s >> 2) * 4;
    const int sc = (s & 3) * 4;
    const int r = r0 + sr + (j >> 2);
    const int c = c0 + sc + (j & 3);
    const float gx = ((float)c + 0.5f) * (1.0f / GW);
    const float gy = ((float)r + 0.5f) * (1.0f / GH);

    float best = 3.4e38f;
    int   bn = 0;
    bool  need_full = ovf;

    if (!ovf) {
        const float scx = ((float)(c0 + sc) + 2.0f) * (1.0f / GW);
        const float scy = ((float)(r0 + sr) + 2.0f) * (1.0f / GH);

        // ---- pass 1: min dist(subtile center, candidate) over all segments ----
        float d2e[8];
        float sm = 3.0e38f;
#pragma unroll
        for (int t = 0; t < 8; ++t) {
            float d2v = 3.0e38f;
            if (j < cnt[t]) {                 // lower half of segment (e = j)
                const float4 q = seg[t * SEGCAP + j];
                const float dx = scx - q.x;
                const float dy = scy - q.y;
                d2v = __fmaf_rn(dy, dy, dx * dx);
            }
            d2e[t] = d2v;
            sm = fminf(sm, d2v);
            if (cnt[t] > 16) {                // rare upper half (e = 16 + j)
                if (16 + j < cnt[t]) {
                    const float4 q = seg[t * SEGCAP + 16 + j];
                    const float dx = scx - q.x;
                    const float dy = scy - q.y;
                    sm = fminf(sm, __fmaf_rn(dy, dy, dx * dx));
                }
            }
        }
#pragma unroll
        for (int o = 8; o > 0; o >>= 1)       // half-warp min
            sm = fminf(sm, __shfl_xor_sync(0xffffffffu, sm, o, 16));
        const float Ts = sqrtf(sm) + 2.0f * RSUB + 1.0e-3f;
        const float th2 = Ts * Ts;

        // ---- pass 2: ballot survivors per segment, exact argmin inline ----
        // (segments ascending, element ascending => ascending point index)
#pragma unroll
        for (int t = 0; t < 8; ++t) {
            const bool f = (j < cnt[t]) && (d2e[t] <= th2);
            unsigned mb = __ballot_sync(0xffffffffu, f) & gmask;
            while (mb) {
                const int bit = __ffs(mb) - 1;
                mb &= mb - 1u;
                const float4 q = seg[t * SEGCAP + (bit & 15)];
                const float dot = __fmaf_rn(gy, q.y, __fmul_rn(gx, q.x));
                const float d2  = __fmaf_rn(-2.0f, dot, q.z);
                if (d2 < best) { best = d2; bn = __float_as_int(q.w); }
            }
            if (cnt[t] > 16) {                // rare upper half
                float d2o = 3.0e38f;
                const bool v2 = (16 + j < cnt[t]);
                if (v2) {
                    const float4 q = seg[t * SEGCAP + 16 + j];
                    const float dx = scx - q.x;
                    const float dy = scy - q.y;
                    d2o = __fmaf_rn(dy, dy, dx * dx);
                }
                unsigned mo = __ballot_sync(0xffffffffu, v2 && (d2o <= th2)) & gmask;
                while (mo) {
                    const int bit = __ffs(mo) - 1;
                    mo &= mo - 1u;
                    const float4 q = seg[t * SEGCAP + 16 + (bit & 15)];
                    const float dot = __fmaf_rn(gy, q.y, __fmul_rn(gx, q.x));
                    const float d2  = __fmaf_rn(-2.0f, dot, q.z);
                    if (d2 < best) { best = d2; bn = __float_as_int(q.w); }
                }
            }
        }

        // ---- a-posteriori exactness check for the fixed radius ----
        const float g2 = __fmaf_rn(gy, gy, gx * gx);
        const float dtrue = sqrtf(fmaxf(best + g2, 0.0f));
        need_full = (dtrue + RTILE + 5.0e-3f > RFIX);
    }

    if (need_full) {                          // exact full scan (vanishingly rare)
        best = 3.4e38f; bn = 0;
        for (int n = 0; n < NPTS; ++n) {
            const float x = __ldg(xp + n);
            const float y = __ldg(yp + n);
            const float pn2 = __fadd_rn(__fmul_rn(x, x), __fmul_rn(y, y));
            const float dot = __fmaf_rn(gy, y, __fmul_rn(gx, x));
            const float d2  = __fmaf_rn(-2.0f, dot, pn2);
            if (d2 < best) { best = d2; bn = n; }
        }
    }

    // ---- gather channels + store ----
    const float* Rb = R + b * (NCH * NPTS);
    const int g = r * GW + c;
#pragma unroll
    for (int ch = 0; ch < NCH; ++ch)
        out[(b * NCH + ch) * (GH * GW) + g] = __ldg(Rb + ch * NPTS + bn);
}

extern "C" void kernel_launch(void* const* d_in, const int* in_sizes, int n_in,
                              void* d_out, int out_size)
{
    const float* R  = (const float*)d_in[0];
    const float* XY = (const float*)d_in[1];
    nn_seg_kernel<<<512, TPB>>>(R, XY, (float*)d_out);
}